// round 7
// baseline (speedup 1.0000x reference)
#include <cuda_runtime.h>
#include <cuda_bf16.h>
#include <cstdint>
#include <cstddef>

// ---------------------------------------------------------------------------
// Problem constants
// ---------------------------------------------------------------------------
#define B_SZ   8192
#define D_SZ   8
#define P_SZ   10
#define R_SZ   512
#define OUT_SZ 64
#define NMID   6
#define KTOT   (P_SZ * R_SZ)   // 5120
#define KC     32              // K per pipeline chunk
#define RCH    (R_SZ / KC)     // 16 chunks per j
#define NCH    (KTOT / KC)     // 160

// ---------------------------------------------------------------------------
// Device-global scratch
// ---------------------------------------------------------------------------
__device__ float g_tanh_g0[P_SZ * R_SZ];
__device__ __nv_bfloat16 g_rh0[(size_t)B_SZ * R_SZ];
__device__ __nv_bfloat16 g_rl0[(size_t)B_SZ * R_SZ];
__device__ __nv_bfloat16 g_rh1[(size_t)B_SZ * R_SZ];
__device__ __nv_bfloat16 g_rl1[(size_t)B_SZ * R_SZ];
__device__ __nv_bfloat16 g_bhi_mid[(size_t)NMID * R_SZ * KTOT];
__device__ __nv_bfloat16 g_blo_mid[(size_t)NMID * R_SZ * KTOT];
__device__ __nv_bfloat16 g_bhi_last[(size_t)OUT_SZ * KTOT];
__device__ __nv_bfloat16 g_blo_last[(size_t)OUT_SZ * KTOT];

// ---------------------------------------------------------------------------
// PTX helpers (sm_80-era: cp.async, ldmatrix, mma.sync — NO tcgen05)
// ---------------------------------------------------------------------------
__device__ __forceinline__ uint32_t smem_u32(const void* p) {
    uint32_t a;
    asm("{ .reg .u64 t; cvta.to.shared.u64 t, %1; cvt.u32.u64 %0, t; }" : "=r"(a) : "l"(p));
    return a;
}
#define CP_ASYNC16(dst, src) \
    asm volatile("cp.async.cg.shared.global [%0], [%1], 16;" :: "r"(dst), "l"(src) : "memory")
#define CP_COMMIT() asm volatile("cp.async.commit_group;" ::: "memory")
#define CP_WAIT1()  asm volatile("cp.async.wait_group 1;" ::: "memory")
#define CP_WAIT2()  asm volatile("cp.async.wait_group 2;" ::: "memory")

#define LDSM4(r0, r1, r2, r3, addr) \
    asm volatile("ldmatrix.sync.aligned.m8n8.x4.shared.b16 {%0,%1,%2,%3}, [%4];" \
                 : "=r"(r0), "=r"(r1), "=r"(r2), "=r"(r3) : "r"(addr))

#define MMA_BF16(d, a, b) \
    asm volatile("mma.sync.aligned.m16n8k16.row.col.f32.bf16.bf16.f32 " \
                 "{%0,%1,%2,%3}, {%4,%5,%6,%7}, {%8,%9}, {%0,%1,%2,%3};" \
                 : "+f"((d)[0]), "+f"((d)[1]), "+f"((d)[2]), "+f"((d)[3]) \
                 : "r"((a)[0]), "r"((a)[1]), "r"((a)[2]), "r"((a)[3]), \
                   "r"((b)[0]), "r"((b)[1]))

// 64B-row XOR swizzle: conflict-free across all 8-row ldmatrix phases.
__device__ __forceinline__ uint32_t sw64(uint32_t row, uint32_t c16) {
    return row * 64u + ((c16 ^ ((row >> 1) & 3u)) << 4);
}

// ---------------------------------------------------------------------------
// Precompute: tanh + bf16 hi/lo split + transpose
//   G [R, P, N] (n contiguous) -> hi/lo [N][j*512 + r] (k contiguous)
// ---------------------------------------------------------------------------
__global__ void split_transpose_kernel(const float* __restrict__ G,
                                       __nv_bfloat16* __restrict__ hi,
                                       __nv_bfloat16* __restrict__ lo,
                                       int N, size_t gStride, size_t oStride) {
    __shared__ float t[32][33];
    int layer = blockIdx.z / P_SZ;
    int j     = blockIdx.z % P_SZ;
    const float* Gp = G + (size_t)layer * gStride;
    __nv_bfloat16* hip = hi + (size_t)layer * oStride;
    __nv_bfloat16* lop = lo + (size_t)layer * oStride;
    int rt = blockIdx.x * 32, nt = blockIdx.y * 32;
    int tx = threadIdx.x, ty = threadIdx.y;   // block (32, 8)
#pragma unroll
    for (int yy = ty; yy < 32; yy += 8)
        t[yy][tx] = tanhf(Gp[((size_t)(rt + yy) * P_SZ + j) * N + nt + tx]);
    __syncthreads();
#pragma unroll
    for (int yy = ty; yy < 32; yy += 8) {
        int n = nt + yy, r = rt + tx;
        float x = t[tx][yy];
        __nv_bfloat16 h = __float2bfloat16_rn(x);
        size_t o = (size_t)n * KTOT + (size_t)j * R_SZ + r;
        hip[o] = h;
        lop[o] = __float2bfloat16_rn(x - __bfloat162float(h));
    }
}

__global__ void tanh_small_kernel(const float* __restrict__ src,
                                  float* __restrict__ dst, int n) {
    int i = blockIdx.x * blockDim.x + threadIdx.x;
    if (i < n) dst[i] = tanhf(src[i]);
}

// First core: res0[b,r] = sum_j tanh(G0)[j,r] * z[b,0]^j, hi/lo split output
__global__ void first_core_kernel(const float* __restrict__ z,
                                  __nv_bfloat16* __restrict__ rh,
                                  __nv_bfloat16* __restrict__ rl) {
    int b = blockIdx.x;
    int r = threadIdx.x;
    float zv = z[b * D_SZ + 0];
    float ph = 1.f, acc = 0.f;
#pragma unroll
    for (int j = 0; j < P_SZ; j++) {
        acc += g_tanh_g0[j * R_SZ + r] * ph;
        ph *= zv;
    }
    __nv_bfloat16 h = __float2bfloat16_rn(acc);
    rh[(size_t)b * R_SZ + r] = h;
    rl[(size_t)b * R_SZ + r] = __float2bfloat16_rn(acc - __bfloat162float(h));
}

// ---------------------------------------------------------------------------
// HMMA bf16 3-product-split GEMM with Horner phi folding.
// NSTAGE-deep cp.async pipeline; MINCTAS CTAs co-resident per SM so one CTA's
// barriers/waits are covered by the other's MMAs.
// EPI 0: write bf16 hi/lo split (feeds next layer). EPI 1: write f32.
// ---------------------------------------------------------------------------
template<int BM, int BN, int WM, int WN, int THREADS, int MINCTAS, int NSTAGE, int EPI>
__global__ void __launch_bounds__(THREADS, MINCTAS)
tt_mma_kernel(const __nv_bfloat16* __restrict__ Ahi,
              const __nv_bfloat16* __restrict__ Alo,
              const __nv_bfloat16* __restrict__ Bhi,
              const __nv_bfloat16* __restrict__ Blo,
              const float* __restrict__ z, int zcol,
              float* __restrict__ outF,
              __nv_bfloat16* __restrict__ outH,
              __nv_bfloat16* __restrict__ outL, int Ntotal) {
    constexpr int MT = WM / 16, NT = WN / 8;
    constexpr int A_T = BM * 64;               // one A tile (hi or lo), bytes
    constexpr int B_T = BN * 64;
    constexpr int STAGE = 2 * A_T + 2 * B_T;

    extern __shared__ __align__(16) char sm[];
    const uint32_t base = smem_u32(sm);

    const int tid = threadIdx.x, lane = tid & 31, wid = tid >> 5;
    const int m0 = blockIdx.y * BM, n0 = blockIdx.x * BN;
    constexpr int NWC = BN / WN;
    const int wm0 = (wid / NWC) * WM;
    const int wn0 = (wid % NWC) * WN;

    // per-lane z values for Horner scaling (rows r, r+8 per mt quad)
    float zA[MT], zB[MT];
#pragma unroll
    for (int mt = 0; mt < MT; mt++) {
        int rA = m0 + wm0 + mt * 16 + (lane >> 2);
        zA[mt] = z[(size_t)rA * D_SZ + zcol];
        zB[mt] = z[(size_t)(rA + 8) * D_SZ + zcol];
    }

    float acc[MT][NT][4];
#pragma unroll
    for (int mt = 0; mt < MT; mt++)
#pragma unroll
        for (int nt = 0; nt < NT; nt++)
#pragma unroll
            for (int q = 0; q < 4; q++) acc[mt][nt][q] = 0.f;

    auto produce = [&](int cc) {
        const int s = cc % NSTAGE;
        const int j = (P_SZ - 1) - cc / RCH;       // descending j
        const int rr = cc & (RCH - 1);
        const int roffA = rr * KC;
        const int koffB = j * R_SZ + rr * KC;
        const uint32_t aH = base + s * STAGE;
        const uint32_t aL = aH + A_T;
        const uint32_t bH = aH + 2 * A_T;
        const uint32_t bL = bH + B_T;
#pragma unroll
        for (int i = 0; i < (BM * 4) / THREADS; i++) {
            const int idx = tid + i * THREADS;
            const int row = idx >> 2, c16 = idx & 3;
            const uint32_t off = sw64(row, c16);
            const size_t go = (size_t)(m0 + row) * R_SZ + roffA + c16 * 8;
            CP_ASYNC16(aH + off, Ahi + go);
            CP_ASYNC16(aL + off, Alo + go);
        }
#pragma unroll
        for (int i = 0; i < (BN * 4) / THREADS; i++) {
            const int idx = tid + i * THREADS;
            const int row = idx >> 2, c16 = idx & 3;
            const uint32_t off = sw64(row, c16);
            const size_t go = (size_t)(n0 + row) * KTOT + koffB + c16 * 8;
            CP_ASYNC16(bH + off, Bhi + go);
            CP_ASYNC16(bL + off, Blo + go);
        }
        CP_COMMIT();
    };

    auto mma_chunk = [&](int s) {
        const uint32_t aH = base + s * STAGE;
        const uint32_t aL = aH + A_T;
        const uint32_t bH = aH + 2 * A_T;
        const uint32_t bL = bH + B_T;
#pragma unroll
        for (int ks = 0; ks < 2; ks++) {
            uint32_t bh[NT][2], bl[NT][2];
#pragma unroll
            for (int n2 = 0; n2 < NT / 2; n2++) {
                const uint32_t rowb = wn0 + n2 * 16 + ((lane >> 4) << 3) + (lane & 7);
                const uint32_t c16b = ((lane >> 3) & 1) + 2 * ks;
                LDSM4(bh[2 * n2][0], bh[2 * n2][1], bh[2 * n2 + 1][0], bh[2 * n2 + 1][1],
                      bH + sw64(rowb, c16b));
                LDSM4(bl[2 * n2][0], bl[2 * n2][1], bl[2 * n2 + 1][0], bl[2 * n2 + 1][1],
                      bL + sw64(rowb, c16b));
            }
            uint32_t a[MT][4];
#pragma unroll
            for (int mt = 0; mt < MT; mt++) {
                const uint32_t rowa = wm0 + mt * 16 + (lane & 15);
                LDSM4(a[mt][0], a[mt][1], a[mt][2], a[mt][3],
                      aH + sw64(rowa, (lane >> 4) + 2 * ks));
            }
#pragma unroll
            for (int mt = 0; mt < MT; mt++)
#pragma unroll
                for (int nt = 0; nt < NT; nt++) MMA_BF16(acc[mt][nt], a[mt], bh[nt]);
#pragma unroll
            for (int mt = 0; mt < MT; mt++)
#pragma unroll
                for (int nt = 0; nt < NT; nt++) MMA_BF16(acc[mt][nt], a[mt], bl[nt]);
#pragma unroll
            for (int mt = 0; mt < MT; mt++) {
                const uint32_t rowa = wm0 + mt * 16 + (lane & 15);
                LDSM4(a[mt][0], a[mt][1], a[mt][2], a[mt][3],
                      aL + sw64(rowa, (lane >> 4) + 2 * ks));
            }
#pragma unroll
            for (int mt = 0; mt < MT; mt++)
#pragma unroll
                for (int nt = 0; nt < NT; nt++) MMA_BF16(acc[mt][nt], a[mt], bh[nt]);
        }
    };

    // prologue: NSTAGE-1 stages in flight
#pragma unroll
    for (int p = 0; p < NSTAGE - 1; p++) produce(p);

    for (int c = 0; c < NCH; c++) {
        if constexpr (NSTAGE == 3) CP_WAIT1(); else CP_WAIT2();
        __syncthreads();
        if (c + NSTAGE - 1 < NCH) produce(c + NSTAGE - 1); else CP_COMMIT();
        if (c && (c & (RCH - 1)) == 0) {
            // Horner: entering next-lower j — scale accumulators by z
#pragma unroll
            for (int mt = 0; mt < MT; mt++)
#pragma unroll
                for (int nt = 0; nt < NT; nt++) {
                    acc[mt][nt][0] *= zA[mt]; acc[mt][nt][1] *= zA[mt];
                    acc[mt][nt][2] *= zB[mt]; acc[mt][nt][3] *= zB[mt];
                }
        }
        mma_chunk(c % NSTAGE);
    }

    // epilogue
#pragma unroll
    for (int mt = 0; mt < MT; mt++) {
        const int row0 = m0 + wm0 + mt * 16 + (lane >> 2);
#pragma unroll
        for (int nt = 0; nt < NT; nt++) {
            const int col = n0 + wn0 + nt * 8 + (lane & 3) * 2;
            if (EPI == 1) {
                *reinterpret_cast<float2*>(&outF[(size_t)row0 * Ntotal + col]) =
                    make_float2(acc[mt][nt][0], acc[mt][nt][1]);
                *reinterpret_cast<float2*>(&outF[(size_t)(row0 + 8) * Ntotal + col]) =
                    make_float2(acc[mt][nt][2], acc[mt][nt][3]);
            } else {
#pragma unroll
                for (int h = 0; h < 2; h++) {
                    const int row = row0 + 8 * h;
                    float v0 = acc[mt][nt][2 * h], v1 = acc[mt][nt][2 * h + 1];
                    __nv_bfloat16 h0 = __float2bfloat16_rn(v0);
                    __nv_bfloat16 h1 = __float2bfloat16_rn(v1);
                    __nv_bfloat162 hv; hv.x = h0; hv.y = h1;
                    __nv_bfloat162 lv;
                    lv.x = __float2bfloat16_rn(v0 - __bfloat162float(h0));
                    lv.y = __float2bfloat16_rn(v1 - __bfloat162float(h1));
                    *reinterpret_cast<__nv_bfloat162*>(&outH[(size_t)row * R_SZ + col]) = hv;
                    *reinterpret_cast<__nv_bfloat162*>(&outL[(size_t)row * R_SZ + col]) = lv;
                }
            }
        }
    }
}

// ---------------------------------------------------------------------------
// Launch (graph-capturable, allocation-free)
// Inputs: z [B,D] f32, G0 [P,R] f32, G_mid [6,R,P,R] f32, G_last [R,P,OUT] f32, t
// Output: [B, OUT] f32
// ---------------------------------------------------------------------------
extern "C" void kernel_launch(void* const* d_in, const int* in_sizes, int n_in,
                              void* d_out, int out_size) {
    (void)in_sizes; (void)n_in; (void)out_size;
    const float* z     = (const float*)d_in[0];
    const float* G0    = (const float*)d_in[1];
    const float* Gmid  = (const float*)d_in[2];
    const float* Glast = (const float*)d_in[3];
    float* out = (float*)d_out;

    float* p_tg0;
    __nv_bfloat16 *p_rh0, *p_rl0, *p_rh1, *p_rl1, *p_bhi, *p_blo, *p_bhiL, *p_bloL;
    cudaGetSymbolAddress((void**)&p_tg0,  g_tanh_g0);
    cudaGetSymbolAddress((void**)&p_rh0,  g_rh0);
    cudaGetSymbolAddress((void**)&p_rl0,  g_rl0);
    cudaGetSymbolAddress((void**)&p_rh1,  g_rh1);
    cudaGetSymbolAddress((void**)&p_rl1,  g_rl1);
    cudaGetSymbolAddress((void**)&p_bhi,  g_bhi_mid);
    cudaGetSymbolAddress((void**)&p_blo,  g_blo_mid);
    cudaGetSymbolAddress((void**)&p_bhiL, g_bhi_last);
    cudaGetSymbolAddress((void**)&p_bloL, g_blo_last);

    // mids: 3 stages x (2*128 + 2*128) rows * 64B = 98304 B -> 2 CTAs/SM
    const int SMEM_MID  = 3 * (2 * 128 + 2 * 128) * 64;  // 98304
    const int SMEM_LAST = 4 * (2 * 64 + 2 * 64) * 64;    // 65536
    cudaFuncSetAttribute((const void*)tt_mma_kernel<128, 128, 64, 32, 256, 2, 3, 0>,
                         cudaFuncAttributeMaxDynamicSharedMemorySize, SMEM_MID);
    cudaFuncSetAttribute((const void*)tt_mma_kernel<64, 64, 32, 16, 256, 1, 4, 1>,
                         cudaFuncAttributeMaxDynamicSharedMemorySize, SMEM_LAST);

    // precompute
    tanh_small_kernel<<<(P_SZ * R_SZ + 255) / 256, 256>>>(G0, p_tg0, P_SZ * R_SZ);
    split_transpose_kernel<<<dim3(R_SZ / 32, R_SZ / 32, NMID * P_SZ), dim3(32, 8)>>>(
        Gmid, p_bhi, p_blo, R_SZ,
        (size_t)R_SZ * P_SZ * R_SZ, (size_t)R_SZ * KTOT);
    split_transpose_kernel<<<dim3(R_SZ / 32, OUT_SZ / 32, P_SZ), dim3(32, 8)>>>(
        Glast, p_bhiL, p_bloL, OUT_SZ, 0, 0);

    // first core -> split res0
    first_core_kernel<<<B_SZ, R_SZ>>>(z, p_rh0, p_rl0);

    // six middle cores (ping-pong on split res) — 256 CTAs, 2 CTAs/SM
    __nv_bfloat16 *ch = p_rh0, *cl = p_rl0, *nh = p_rh1, *nl = p_rl1;
    for (int i = 0; i < NMID; i++) {
        tt_mma_kernel<128, 128, 64, 32, 256, 2, 3, 0>
            <<<dim3(R_SZ / 128, B_SZ / 128), 256, SMEM_MID>>>(
            ch, cl,
            p_bhi + (size_t)i * R_SZ * KTOT, p_blo + (size_t)i * R_SZ * KTOT,
            z, i + 1, nullptr, nh, nl, R_SZ);
        __nv_bfloat16* t;
        t = ch; ch = nh; nh = t;
        t = cl; cl = nl; nl = t;
    }

    // last core -> d_out [B, OUT] f32
    tt_mma_kernel<64, 64, 32, 16, 256, 1, 4, 1><<<dim3(1, B_SZ / 64), 256, SMEM_LAST>>>(
        ch, cl, p_bhiL, p_bloL, z, D_SZ - 1, out, nullptr, nullptr, OUT_SZ);
}